// round 2
// baseline (speedup 1.0000x reference)
#include <cuda_runtime.h>
#include <math.h>

// ---------------- scratch (device globals; no allocations) ----------------
#define NB 16
__device__ float g_h1[NB*64*256*256];   // 256 MB
__device__ float g_h2[NB*128*128*128];  // 128 MB
__device__ float g_h3[NB*256*64*64];    //  64 MB
__device__ float g_z [NB*512*32*32];    //  32 MB
__device__ float g_zf[NB*1024*512];     //  32 MB  (16384 x 512 row-major)
__device__ float g_zq[NB*512*32*32];    //  32 MB
__device__ float g_g1[NB*256*64*64];    //  64 MB
__device__ float g_g2[NB*128*128*128];  // 128 MB
__device__ float g_g3[NB*64*256*256];   // 256 MB
__device__ float g_cn[8192];
__device__ int   g_idx[16384];

typedef unsigned long long ull;

// ---------------- f32x2 packed helpers ----------------
__device__ __forceinline__ ull fma2(ull a, ull b, ull c) {
    ull d;
    asm("fma.rn.f32x2 %0, %1, %2, %3;" : "=l"(d) : "l"(a), "l"(b), "l"(c));
    return d;
}
__device__ __forceinline__ ull splat2(float v) {
    ull d; unsigned int u = __float_as_uint(v);
    asm("mov.b64 %0, {%1, %1};" : "=l"(d) : "r"(u));
    return d;
}
__device__ __forceinline__ ull pack2(float lo, float hi) {
    ull d;
    asm("mov.b64 %0, {%1, %2};" : "=l"(d)
        : "r"(__float_as_uint(lo)), "r"(__float_as_uint(hi)));
    return d;
}
__device__ __forceinline__ void unpack2(ull v, float& lo, float& hi) {
    unsigned int a, b;
    asm("mov.b64 {%0, %1}, %2;" : "=r"(a), "=r"(b) : "l"(v));
    lo = __uint_as_float(a); hi = __uint_as_float(b);
}

// ---------------- direct 3x3 conv, pad=1, FFMA2 oc-paired ----------------
// Thread: 4 horizontal outputs x TC output channels (TC even).
// Weights in smem laid out [ci][tap][oc] so LDS.64 gives {w_oc, w_oc+1}.
// ACT: 0 none, 1 relu
template<int STRIDE, int TC, int ACT>
__global__ void __launch_bounds__(128) conv2x_k(
    const float* __restrict__ in, const float* __restrict__ wgt,
    const float* __restrict__ bias, float* __restrict__ out,
    int Cin, int Cout, int Hin, int Win, int Hout, int Wout)
{
    constexpr int CICH = 32;
    constexpr int NC = (STRIDE == 1) ? 6 : 9;
    constexpr int TP = TC / 2;
    __shared__ ull ws2[CICH * 9 * TP];
    float* wsf = (float*)ws2;

    const int tid  = threadIdx.x;
    const int W4   = Wout >> 2;
    const int rows = 128 / W4;
    const int lane = tid % W4;
    const int row  = tid / W4;
    const int oy   = blockIdx.y * rows + row;
    const int ox0  = lane * 4;
    const int ocg  = blockIdx.x * TC;
    const int n    = blockIdx.z;

    ull acc2[TP][4];
#pragma unroll
    for (int p = 0; p < TP; p++)
#pragma unroll
        for (int j = 0; j < 4; j++) acc2[p][j] = 0ull;

    bool cval[NC];
#pragma unroll
    for (int c = 0; c < NC; c++) {
        int ix = ox0 * STRIDE + c - 1;
        cval[c] = (ix >= 0 && ix < Win);
    }
    const int ixbase = ox0 * STRIDE - 1;
    bool rval[3]; int iyo[3];
#pragma unroll
    for (int ky = 0; ky < 3; ky++) {
        int iy = oy * STRIDE + ky - 1;
        rval[ky] = (iy >= 0 && iy < Hin);
        iyo[ky] = iy;
    }

    auto loadRaw = [&](float (&raw)[3][NC], int cabs) {
        const float* ip = in + ((size_t)n * Cin + cabs) * Hin * Win;
#pragma unroll
        for (int ky = 0; ky < 3; ky++) {
            const float* rp = ip + (long)iyo[ky] * Win + ixbase;
#pragma unroll
            for (int c = 0; c < NC; c++)
                raw[ky][c] = (rval[ky] && cval[c]) ? rp[c] : 0.f;
        }
    };
    auto computeCi = [&](float (&raw)[3][NC], int ci) {
#pragma unroll
        for (int ky = 0; ky < 3; ky++) {
            ull iv2[NC];
#pragma unroll
            for (int c = 0; c < NC; c++) iv2[c] = splat2(raw[ky][c]);
#pragma unroll
            for (int p = 0; p < TP; p++) {
#pragma unroll
                for (int kx = 0; kx < 3; kx++) {
                    ull w2 = ws2[(ci * 9 + ky * 3 + kx) * TP + p];
#pragma unroll
                    for (int j = 0; j < 4; j++)
                        acc2[p][j] = fma2(iv2[j * STRIDE + kx], w2, acc2[p][j]);
                }
            }
        }
    };

    float rawA[3][NC], rawB[3][NC];
    for (int cc = 0; cc < Cin; cc += CICH) {
        const int chunk = min(CICH, Cin - cc);
        __syncthreads();
        for (int i = tid; i < chunk * 9 * TC; i += 128) {
            int ci = i / (9 * TC);
            int r  = i - ci * (9 * TC);
            int k  = r / TC;
            int oc = r - k * TC;
            wsf[i] = wgt[(size_t)(ocg + oc) * Cin * 9 + (size_t)(cc + ci) * 9 + k];
        }
        __syncthreads();
        loadRaw(rawA, cc);
        for (int ci = 0; ci < chunk; ci += 2) {
            if (ci + 1 < chunk) loadRaw(rawB, cc + ci + 1);
            computeCi(rawA, ci);
            if (ci + 2 < chunk) loadRaw(rawA, cc + ci + 2);
            if (ci + 1 < chunk) computeCi(rawB, ci + 1);
        }
    }

#pragma unroll
    for (int p = 0; p < TP; p++) {
        float b0 = bias[ocg + 2 * p];
        float b1 = bias[ocg + 2 * p + 1];
        float* o0 = out + (((size_t)n * Cout + ocg + 2 * p) * Hout + oy) * Wout + ox0;
        float* o1 = o0 + (size_t)Hout * Wout;
#pragma unroll
        for (int j = 0; j < 4; j++) {
            float lo, hi; unpack2(acc2[p][j], lo, hi);
            float v0 = lo + b0, v1 = hi + b1;
            if (ACT == 1) { v0 = v0 > 0.f ? v0 : 0.f; v1 = v1 > 0.f ? v1 : 0.f; }
            o0[j] = v0; o1[j] = v1;
        }
    }
}

// ---------------- scalar conv (for final 3-channel sigmoid layer) -------------
template<int STRIDE, int TC, int ACT>
__global__ void __launch_bounds__(128) convS_k(
    const float* __restrict__ in, const float* __restrict__ wgt,
    const float* __restrict__ bias, float* __restrict__ out,
    int Cin, int Cout, int Hin, int Win, int Hout, int Wout)
{
    constexpr int CICH = 32;
    constexpr int NC = (STRIDE == 1) ? 6 : 9;
    __shared__ float ws[CICH * TC * 9];

    const int tid  = threadIdx.x;
    const int W4   = Wout >> 2;
    const int rows = 128 / W4;
    const int lane = tid % W4;
    const int row  = tid / W4;
    const int oy   = blockIdx.y * rows + row;
    const int ox0  = lane * 4;
    const int ocg  = blockIdx.x * TC;
    const int n    = blockIdx.z;

    float acc[TC][4];
#pragma unroll
    for (int a = 0; a < TC; a++)
#pragma unroll
        for (int j = 0; j < 4; j++) acc[a][j] = 0.f;

    bool cval[NC];
#pragma unroll
    for (int c = 0; c < NC; c++) {
        int ix = ox0 * STRIDE + c - 1;
        cval[c] = (ix >= 0 && ix < Win);
    }
    const int ixbase = ox0 * STRIDE - 1;
    bool rval[3]; int iyo[3];
#pragma unroll
    for (int ky = 0; ky < 3; ky++) {
        int iy = oy * STRIDE + ky - 1;
        rval[ky] = (iy >= 0 && iy < Hin);
        iyo[ky] = iy;
    }

    for (int cc = 0; cc < Cin; cc += CICH) {
        const int chunk = min(CICH, Cin - cc);
        __syncthreads();
        for (int i = tid; i < chunk * TC * 9; i += 128) {
            int ci = i / (TC * 9);
            int r  = i - ci * (TC * 9);
            int oc = r / 9;
            int k  = r - oc * 9;
            ws[i] = wgt[(size_t)(ocg + oc) * Cin * 9 + (size_t)(cc + ci) * 9 + k];
        }
        __syncthreads();
        for (int ci = 0; ci < chunk; ci++) {
            const float* ip = in + ((size_t)n * Cin + cc + ci) * Hin * Win;
            float iv[3][NC];
#pragma unroll
            for (int ky = 0; ky < 3; ky++) {
                const float* rp = ip + (long)iyo[ky] * Win + ixbase;
#pragma unroll
                for (int c = 0; c < NC; c++)
                    iv[ky][c] = (rval[ky] && cval[c]) ? rp[c] : 0.f;
            }
            const float* wp = ws + ci * TC * 9;
#pragma unroll
            for (int oc = 0; oc < TC; oc++) {
#pragma unroll
                for (int ky = 0; ky < 3; ky++)
#pragma unroll
                    for (int kx = 0; kx < 3; kx++) {
                        float wv = wp[oc * 9 + ky * 3 + kx];
#pragma unroll
                        for (int j = 0; j < 4; j++)
                            acc[oc][j] = fmaf(iv[ky][j * STRIDE + kx], wv, acc[oc][j]);
                    }
            }
        }
    }
#pragma unroll
    for (int oc = 0; oc < TC; oc++) {
        float bv = bias[ocg + oc];
        float* op = out + (((size_t)n * Cout + ocg + oc) * Hout + oy) * Wout + ox0;
#pragma unroll
        for (int j = 0; j < 4; j++) {
            float v = acc[oc][j] + bv;
            if (ACT == 1) v = v > 0.f ? v : 0.f;
            if (ACT == 2) v = 1.f / (1.f + expf(-v));
            op[j] = v;
        }
    }
}

// ---------------- transposed conv k=3 s=2 p=1 op=1, FFMA2 oc-paired -----------
template<int TC, int ACT>
__global__ void __launch_bounds__(128) deconv2x_k(
    const float* __restrict__ in, const float* __restrict__ wgt,  // [Cin][Cout][3][3]
    const float* __restrict__ bias, float* __restrict__ out,
    int Cin, int Cout, int Hin, int Win)
{
    constexpr int CICH = 32;
    constexpr int TP = TC / 2;
    __shared__ ull ws2[CICH * 9 * TP];
    float* wsf = (float*)ws2;

    const int Hout = Hin * 2, Wout = Win * 2;
    const int tid  = threadIdx.x;
    const int W4   = Wout >> 2;
    const int rows = 128 / W4;
    const int q    = tid % W4;
    const int a    = blockIdx.y * rows + tid / W4;  // input row
    const int b    = q * 2;                          // input col base
    const int ocg  = blockIdx.x * TC;
    const int n    = blockIdx.z;

    const bool v_a1 = (a + 1) < Hin;
    const bool v_b2 = (b + 2) < Win;

    ull acc2[TP][8];
#pragma unroll
    for (int p = 0; p < TP; p++)
#pragma unroll
        for (int j = 0; j < 8; j++) acc2[p][j] = 0ull;

    auto loadRaw = [&](float (&rw)[6], int cabs) {
        const float* ip = in + ((size_t)n * Cin + cabs) * Hin * Win;
        const float* r0 = ip + (size_t)a * Win + b;
        rw[0] = r0[0];
        rw[1] = r0[1];
        rw[2] = v_b2 ? r0[2] : 0.f;
        if (v_a1) {
            const float* r1 = r0 + Win;
            rw[3] = r1[0]; rw[4] = r1[1]; rw[5] = v_b2 ? r1[2] : 0.f;
        } else {
            rw[3] = 0.f; rw[4] = 0.f; rw[5] = 0.f;
        }
    };
    auto computeCi = [&](float (&rw)[6], int ci) {
        ull s00 = splat2(rw[0]), s01 = splat2(rw[1]), s02 = splat2(rw[2]);
        ull s10 = splat2(rw[3]), s11 = splat2(rw[4]), s12 = splat2(rw[5]);
        const ull* wp = ws2 + (size_t)ci * 9 * TP;
#pragma unroll
        for (int p = 0; p < TP; p++) {
            ull w00 = wp[0*TP+p], w01 = wp[1*TP+p], w02 = wp[2*TP+p];
            ull w10 = wp[3*TP+p], w11 = wp[4*TP+p], w12 = wp[5*TP+p];
            ull w20 = wp[6*TP+p], w21 = wp[7*TP+p], w22 = wp[8*TP+p];
            acc2[p][0] = fma2(s00, w11, acc2[p][0]);
            acc2[p][1] = fma2(s00, w12, fma2(s01, w10, acc2[p][1]));
            acc2[p][2] = fma2(s01, w11, acc2[p][2]);
            acc2[p][3] = fma2(s01, w12, fma2(s02, w10, acc2[p][3]));
            acc2[p][4] = fma2(s00, w21, fma2(s10, w01, acc2[p][4]));
            acc2[p][5] = fma2(s00, w22, fma2(s01, w20, fma2(s10, w02, fma2(s11, w00, acc2[p][5]))));
            acc2[p][6] = fma2(s01, w21, fma2(s11, w01, acc2[p][6]));
            acc2[p][7] = fma2(s01, w22, fma2(s02, w20, fma2(s11, w02, fma2(s12, w00, acc2[p][7]))));
        }
    };

    float rawA[6], rawB[6];
    for (int cc = 0; cc < Cin; cc += CICH) {
        const int chunk = min(CICH, Cin - cc);
        __syncthreads();
        for (int i = tid; i < chunk * 9 * TC; i += 128) {
            int ci = i / (9 * TC);
            int r  = i - ci * (9 * TC);
            int k  = r / TC;
            int oc = r - k * TC;
            wsf[i] = wgt[(size_t)(cc + ci) * Cout * 9 + (size_t)(ocg + oc) * 9 + k];
        }
        __syncthreads();
        loadRaw(rawA, cc);
        for (int ci = 0; ci < chunk; ci += 2) {
            if (ci + 1 < chunk) loadRaw(rawB, cc + ci + 1);
            computeCi(rawA, ci);
            if (ci + 2 < chunk) loadRaw(rawA, cc + ci + 2);
            if (ci + 1 < chunk) computeCi(rawB, ci + 1);
        }
    }

#pragma unroll
    for (int p = 0; p < TP; p++) {
        float b0 = bias[ocg + 2 * p];
        float b1 = bias[ocg + 2 * p + 1];
        float* o0 = out + (((size_t)n * Cout + ocg + 2 * p) * Hout + 2 * a) * Wout + 4 * q;
        float* o1 = o0 + (size_t)Hout * Wout;
#pragma unroll
        for (int j = 0; j < 4; j++) {
            float lo, hi; unpack2(acc2[p][j], lo, hi);
            float v0 = lo + b0, v1 = hi + b1;
            if (ACT == 1) { v0 = v0 > 0.f ? v0 : 0.f; v1 = v1 > 0.f ? v1 : 0.f; }
            o0[j] = v0; o1[j] = v1;
        }
        o0 += Wout; o1 += Wout;
#pragma unroll
        for (int j = 0; j < 4; j++) {
            float lo, hi; unpack2(acc2[p][4 + j], lo, hi);
            float v0 = lo + b0, v1 = hi + b1;
            if (ACT == 1) { v0 = v0 > 0.f ? v0 : 0.f; v1 = v1 > 0.f ? v1 : 0.f; }
            o0[j] = v0; o1[j] = v1;
        }
    }
}

// ---------------- z [B,512,32,32] -> zf [16384, 512] (channels-last rows) -------
__global__ void __launch_bounds__(256) zt_k(const float* __restrict__ z,
                                            float* __restrict__ zf)
{
    __shared__ float t[128 * 33];
    const int blk = blockIdx.x;        // b*32 + y
    const int bb  = blk >> 5;
    const int y   = blk & 31;
    const int tid = threadIdx.x;
    for (int cc = 0; cc < 512; cc += 128) {
        __syncthreads();
        for (int i = tid; i < 128 * 32; i += 256) {
            int c = i >> 5, x = i & 31;
            t[c * 33 + x] = z[(((size_t)bb * 512 + cc + c) * 32 + y) * 32 + x];
        }
        __syncthreads();
        for (int i = tid; i < 32 * 128; i += 256) {
            int x = i >> 7, c = i & 127;
            zf[((size_t)bb * 1024 + y * 32 + x) * 512 + cc + c] = t[c * 33 + x];
        }
    }
}

// ---------------- codebook row norms ----------------
__global__ void __launch_bounds__(256) cnorm_k(const float* __restrict__ cb,
                                               float* __restrict__ cn)
{
    const int warp = threadIdx.x >> 5, lane = threadIdx.x & 31;
    const int code = blockIdx.x * 8 + warp;
    const float* p = cb + (size_t)code * 512;
    float s = 0.f;
    for (int d = lane; d < 512; d += 32) { float v = p[d]; s = fmaf(v, v, s); }
#pragma unroll
    for (int o = 16; o > 0; o >>= 1) s += __shfl_xor_sync(0xffffffffu, s, o);
    if (lane == 0) cn[code] = s;
}

// ---------------- quantizer: FFMA2, 16 rows/block, 4 codes/thread ----------------
// smem: zs2 = 16 rows x 512 dims as {z,z} pairs (64KB), cbs = 1024 codes x 32 dims (132KB)
__global__ void __launch_bounds__(256) quant_k(const float* __restrict__ zf,
                                               const float* __restrict__ cb,
                                               const float* __restrict__ cn,
                                               int* __restrict__ idx)
{
    extern __shared__ ull smq[];
    ull* zs2 = smq;                      // 8192 ull
    float* cbs = (float*)(smq + 8192);   // 1024*33 floats
    const int tid = threadIdx.x;
    const int r0  = blockIdx.x * 16;

    for (int i = tid; i < 16 * 512; i += 256) zs2[i] = splat2(zf[(size_t)r0 * 512 + i]);

    float best[16]; int bi[16];
#pragma unroll
    for (int r = 0; r < 16; r++) { best[r] = 3.4e38f; bi[r] = 0; }

    for (int ct = 0; ct < 8; ct++) {
        const int cbase = ct * 1024;
        ull dotA[16], dotB[16];
#pragma unroll
        for (int r = 0; r < 16; r++) { dotA[r] = 0ull; dotB[r] = 0ull; }
        for (int dt = 0; dt < 16; dt++) {
            __syncthreads();
            for (int i = tid; i < 1024 * 32; i += 256) {
                int c = i >> 5, d = i & 31;
                cbs[c * 33 + d] = cb[(size_t)(cbase + c) * 512 + dt * 32 + d];
            }
            __syncthreads();
#pragma unroll 2
            for (int d = 0; d < 32; d++) {
                ull cA = pack2(cbs[tid * 33 + d],        cbs[(tid + 256) * 33 + d]);
                ull cB = pack2(cbs[(tid + 512) * 33 + d], cbs[(tid + 768) * 33 + d]);
                const ull* zp = zs2 + dt * 32 + d;
#pragma unroll
                for (int r = 0; r < 16; r++) {
                    ull zv = zp[(size_t)r * 512];
                    dotA[r] = fma2(zv, cA, dotA[r]);
                    dotB[r] = fma2(zv, cB, dotB[r]);
                }
            }
        }
        float nA0 = cn[cbase + tid],       nA1 = cn[cbase + 256 + tid];
        float nB0 = cn[cbase + 512 + tid], nB1 = cn[cbase + 768 + tid];
#pragma unroll
        for (int r = 0; r < 16; r++) {
            float aLo, aHi, bLo, bHi;
            unpack2(dotA[r], aLo, aHi);
            unpack2(dotB[r], bLo, bHi);
            float s0 = nA0 - 2.f * aLo;
            float s1 = nA1 - 2.f * aHi;
            float s2 = nB0 - 2.f * bLo;
            float s3 = nB1 - 2.f * bHi;
            if (s0 < best[r]) { best[r] = s0; bi[r] = cbase + tid; }
            if (s1 < best[r]) { best[r] = s1; bi[r] = cbase + 256 + tid; }
            if (s2 < best[r]) { best[r] = s2; bi[r] = cbase + 512 + tid; }
            if (s3 < best[r]) { best[r] = s3; bi[r] = cbase + 768 + tid; }
        }
    }
    // block-wide argmin per row (lowest index on ties, matching argmin)
    float* sv = (float*)smq;
    int*   si = (int*)(sv + 256);
    for (int r = 0; r < 16; r++) {
        __syncthreads();
        sv[tid] = best[r]; si[tid] = bi[r];
        __syncthreads();
        for (int s = 128; s > 0; s >>= 1) {
            if (tid < s) {
                float ov = sv[tid + s]; int oi = si[tid + s];
                if (ov < sv[tid] || (ov == sv[tid] && oi < si[tid])) { sv[tid] = ov; si[tid] = oi; }
            }
            __syncthreads();
        }
        if (tid == 0) idx[r0 + r] = si[0];
    }
}

// ---------------- zq gather: zq[b][c][y][x] = cb[idx[n]][c] ----------------
__global__ void __launch_bounds__(256) zqg_k(const float* __restrict__ cb,
                                             const int* __restrict__ idx,
                                             float* __restrict__ zq)
{
    size_t i = (size_t)blockIdx.x * 256 + threadIdx.x;
    if (i >= (size_t)NB * 512 * 32 * 32) return;
    int x = (int)(i & 31);
    int y = (int)((i >> 5) & 31);
    int c = (int)((i >> 10) & 511);
    int bb = (int)(i >> 19);
    int n = bb * 1024 + y * 32 + x;
    zq[i] = cb[(size_t)idx[n] * 512 + c];
}

// ---------------- indices -> tail of output (as float) ----------------
__global__ void __launch_bounds__(256) idxout_k(const int* __restrict__ idx,
                                                float* __restrict__ out,
                                                long out_off, long out_size)
{
    int i = blockIdx.x * 256 + threadIdx.x;
    if (i < 16384 && out_off + i < out_size) out[out_off + i] = (float)idx[i];
}

// ---------------- host launcher ----------------
extern "C" void kernel_launch(void* const* d_in, const int* in_sizes, int n_in,
                              void* d_out, int out_size)
{
    const float* x  = (const float*)d_in[0];
    const float* w1 = (const float*)d_in[1];  const float* b1 = (const float*)d_in[2];
    const float* w2 = (const float*)d_in[3];  const float* b2 = (const float*)d_in[4];
    const float* w3 = (const float*)d_in[5];  const float* b3 = (const float*)d_in[6];
    const float* w4 = (const float*)d_in[7];  const float* b4 = (const float*)d_in[8];
    const float* cb = (const float*)d_in[9];
    const float* d1w = (const float*)d_in[10]; const float* d1b = (const float*)d_in[11];
    const float* d2w = (const float*)d_in[12]; const float* d2b = (const float*)d_in[13];
    const float* d3w = (const float*)d_in[14]; const float* d3b = (const float*)d_in[15];
    const float* wo = (const float*)d_in[16]; const float* bo = (const float*)d_in[17];
    float* out = (float*)d_out;

    float *h1, *h2, *h3, *z, *zf, *zq, *g1, *g2, *g3, *cn;
    int* idx;
    cudaGetSymbolAddress((void**)&h1, g_h1);
    cudaGetSymbolAddress((void**)&h2, g_h2);
    cudaGetSymbolAddress((void**)&h3, g_h3);
    cudaGetSymbolAddress((void**)&z,  g_z);
    cudaGetSymbolAddress((void**)&zf, g_zf);
    cudaGetSymbolAddress((void**)&zq, g_zq);
    cudaGetSymbolAddress((void**)&g1, g_g1);
    cudaGetSymbolAddress((void**)&g2, g_g2);
    cudaGetSymbolAddress((void**)&g3, g_g3);
    cudaGetSymbolAddress((void**)&cn, g_cn);
    cudaGetSymbolAddress((void**)&idx, g_idx);

    // Encoder
    conv2x_k<1, 8, 1><<<dim3(8, 128, NB), 128>>>(x,  w1, b1, h1,   3,  64, 256, 256, 256, 256);
    conv2x_k<2, 8, 1><<<dim3(16, 32, NB), 128>>>(h1, w2, b2, h2,  64, 128, 256, 256, 128, 128);
    conv2x_k<2, 8, 1><<<dim3(32,  8, NB), 128>>>(h2, w3, b3, h3, 128, 256, 128, 128,  64,  64);
    conv2x_k<2, 8, 0><<<dim3(64,  2, NB), 128>>>(h3, w4, b4, z,  256, 512,  64,  64,  32,  32);

    // Quantize
    zt_k<<<512, 256>>>(z, zf);
    cnorm_k<<<1024, 256>>>(cb, cn);
    cudaFuncSetAttribute(quant_k, cudaFuncAttributeMaxDynamicSharedMemorySize, 200704);
    quant_k<<<1024, 256, 200704>>>(zf, cb, cn, idx);
    zqg_k<<<(NB * 512 * 32 * 32 + 255) / 256, 256>>>(cb, idx, zq);

    // Decoder
    deconv2x_k<8, 1><<<dim3(32,  4, NB), 128>>>(zq, d1w, d1b, g1, 512, 256,  32,  32);
    deconv2x_k<8, 1><<<dim3(16, 16, NB), 128>>>(g1, d2w, d2b, g2, 256, 128,  64,  64);
    deconv2x_k<8, 1><<<dim3( 8, 64, NB), 128>>>(g2, d3w, d3b, g3, 128,  64, 128, 128);
    convS_k<1, 3, 2><<<dim3(1, 128, NB), 128>>>(g3, wo, bo, out, 64, 3, 256, 256, 256, 256);

    // Indices appended after reconstruction (concat output convention)
    idxout_k<<<64, 256>>>(idx, out, (long)NB * 3 * 256 * 256, (long)out_size);
}